// round 3
// baseline (speedup 1.0000x reference)
#include <cuda_runtime.h>

// Problem constants (fixed for this problem instance)
#define CCH 64      // channels
#define NI  16      // irreps
#define NK2 120
#define NK1 8
#define NK0 4

// Precomputed channel-dependent tables (scratch; __device__ globals are allowed)
__device__ float g_A2[CCH * NI * NI * NI];  // [c][x][y][i], 1 MB
__device__ float g_c1[CCH * NI * NI];       // [c][x][y]
__device__ float g_c0[CCH * NI];            // [c][x]

typedef unsigned long long ull;

__device__ __forceinline__ ull pack2(float lo, float hi) {
    ull r; asm("mov.b64 %0,{%1,%2};" : "=l"(r) : "f"(lo), "f"(hi)); return r;
}
__device__ __forceinline__ ull dup2(float v) { return pack2(v, v); }
__device__ __forceinline__ void unpack2(ull v, float& lo, float& hi) {
    asm("mov.b64 {%0,%1},%2;" : "=f"(lo), "=f"(hi) : "l"(v));
}
// Packed dual-FMA: two independent fp32 FMAs in one instruction (sm_100+)
__device__ __forceinline__ ull fma2(ull a, ull b, ull c) {
    ull d; asm("fma.rn.f32x2 %0,%1,%2,%3;" : "=l"(d) : "l"(a), "l"(b), "l"(c)); return d;
}
__device__ __forceinline__ ull add2(ull a, ull b) {
    ull d; asm("add.rn.f32x2 %0,%1,%2;" : "=l"(d) : "l"(a), "l"(b)); return d;
}

// ---------------------------------------------------------------------------
// Precompute A2[c,x,y,i] = sum_k U2[x,y,i,k] * w2[k,c]
//            c1[c,x,y]   = sum_k U1[x,y,k]   * w1[k,c]
//            c0[c,x]     = sum_k U0[x,k]     * w0[k,c]
// One block per channel c (64 blocks, 256 threads).
// ---------------------------------------------------------------------------
__global__ void precompute_kernel(const float* __restrict__ U2,
                                  const float* __restrict__ U1,
                                  const float* __restrict__ U0,
                                  const float* __restrict__ w2,
                                  const float* __restrict__ w1,
                                  const float* __restrict__ w0) {
    const int c = blockIdx.x;
    const int tid = threadIdx.x;

    __shared__ float sw2[NK2];
    __shared__ float sw1[NK1];
    __shared__ float sw0[NK0];
    if (tid < NK2) sw2[tid] = w2[tid * CCH + c];
    if (tid < NK1) sw1[tid] = w1[tid * CCH + c];
    if (tid < NK0) sw0[tid] = w0[tid * CCH + c];
    __syncthreads();

    // A2: 4096 outputs per channel, 120-term dot each
    for (int j = tid; j < NI * NI * NI; j += 256) {
        const float* u = U2 + (size_t)j * NK2;
        float acc = 0.f;
        #pragma unroll 8
        for (int k = 0; k < NK2; k++) acc += u[k] * sw2[k];
        g_A2[(size_t)c * (NI * NI * NI) + j] = acc;
    }
    // c1: 256 outputs
    {
        const float* u = U1 + tid * NK1;
        float acc = 0.f;
        #pragma unroll
        for (int k = 0; k < NK1; k++) acc += u[k] * sw1[k];
        g_c1[c * (NI * NI) + tid] = acc;
    }
    // c0: 16 outputs
    if (tid < NI) {
        const float* u = U0 + tid * NK0;
        float acc = 0.f;
        #pragma unroll
        for (int k = 0; k < NK0; k++) acc += u[k] * sw0[k];
        g_c0[c * NI + tid] = acc;
    }
}

// ---------------------------------------------------------------------------
// Main contraction. Block = (channel c, tile of 256 atoms), 128 threads.
// Each thread processes TWO atoms packed into f32x2 lanes.
// A2 lives in shared memory duplicated into both f32x2 halves so LDS.128
// yields two ready packed multipliers (no per-FMA pack MOVs).
// All threads read the same shared address each step -> broadcast (conflict-free).
// ---------------------------------------------------------------------------
__global__ __launch_bounds__(128)
void contract_kernel(const float* __restrict__ feats,
                     float* __restrict__ out,
                     int Natoms) {
    const int c = blockIdx.y;
    const int tid = threadIdx.x;

    __shared__ __align__(16) ull sA2[NI * NI * NI];  // 32 KB (duplicated pairs)
    __shared__ float sc1[NI * NI];                   // 1 KB
    __shared__ float sc0[NI];

    {
        const float* a2g = g_A2 + (size_t)c * (NI * NI * NI);
        for (int j = tid; j < NI * NI * NI; j += 128) sA2[j] = dup2(a2g[j]);
        for (int j = tid; j < NI * NI; j += 128) sc1[j] = g_c1[c * (NI * NI) + j];
        if (tid < NI) sc0[tid] = g_c0[c * NI + tid];
    }
    __syncthreads();

    const int n0 = blockIdx.x * 256 + tid;
    const int n1 = n0 + 128;
    const bool v0 = n0 < Natoms;
    const bool v1 = n1 < Natoms;

    // Load f for both atoms (16 contiguous floats each -> 4x float4)
    float4 fa[4], fb[4];
    {
        const float4* p0 = (const float4*)(feats + ((size_t)n0 * CCH + c) * NI);
        const float4* p1 = (const float4*)(feats + ((size_t)n1 * CCH + c) * NI);
        #pragma unroll
        for (int t = 0; t < 4; t++) {
            fa[t] = v0 ? p0[t] : make_float4(0.f, 0.f, 0.f, 0.f);
            fb[t] = v1 ? p1[t] : make_float4(0.f, 0.f, 0.f, 0.f);
        }
    }
    ull fp[NI];
    #pragma unroll
    for (int t = 0; t < 4; t++) {
        fp[4 * t + 0] = pack2(fa[t].x, fb[t].x);
        fp[4 * t + 1] = pack2(fa[t].y, fb[t].y);
        fp[4 * t + 2] = pack2(fa[t].z, fb[t].z);
        fp[4 * t + 3] = pack2(fa[t].w, fb[t].w);
    }

    ull acc = pack2(0.f, 0.f);
    #pragma unroll 1
    for (int x = 0; x < NI; x++) {
        ull vx = pack2(0.f, 0.f);
        const ull* rowbase = sA2 + x * (NI * NI);
        const float* c1row = sc1 + x * NI;
        #pragma unroll
        for (int y = 0; y < NI; y++) {
            // m = c1[c,x,y] + sum_i A2[c,x,y,i] * f_i   (dual-atom packed)
            ull m = dup2(c1row[y]);
            const ulonglong2* r = (const ulonglong2*)(rowbase + y * NI);
            #pragma unroll
            for (int t = 0; t < 8; t++) {
                ulonglong2 p = r[t];            // LDS.128: two duplicated A2 pairs
                m = fma2(p.x, fp[2 * t + 0], m);
                m = fma2(p.y, fp[2 * t + 1], m);
            }
            vx = fma2(m, fp[y], vx);            // v[x] += (c1+M[x,y]) * f_y
        }
        ull w = add2(vx, dup2(sc0[x]));
        acc = fma2(w, fp[x], acc);              // out += (c0[x]+v[x]) * f_x
    }

    float r0, r1;
    unpack2(acc, r0, r1);
    if (v0) out[(size_t)n0 * CCH + c] = r0;
    if (v1) out[(size_t)n1 * CCH + c] = r1;
}

extern "C" void kernel_launch(void* const* d_in, const int* in_sizes, int n_in,
                              void* d_out, int out_size) {
    const float* feats = (const float*)d_in[0];  // [N, C, I]
    const float* U2    = (const float*)d_in[1];  // [I, I, I, K2]
    const float* U1    = (const float*)d_in[2];  // [I, I, K1]
    const float* U0    = (const float*)d_in[3];  // [I, K0]
    const float* w2    = (const float*)d_in[4];  // [K2, C]
    const float* w1    = (const float*)d_in[5];  // [K1, C]
    const float* w0    = (const float*)d_in[6];  // [K0, C]
    float* out = (float*)d_out;                  // [N, C]

    const int Natoms = in_sizes[0] / (CCH * NI);

    precompute_kernel<<<CCH, 256>>>(U2, U1, U0, w2, w1, w0);

    dim3 grid((Natoms + 255) / 256, CCH);
    contract_kernel<<<grid, 128>>>(feats, out, Natoms);
}

// round 4
// speedup vs baseline: 1.7188x; 1.7188x over previous
#include <cuda_runtime.h>

// Problem constants (fixed for this problem instance)
#define CCH 64      // channels
#define NI  16      // irreps
#define NK2 120
#define NK1 8
#define NK0 4

// Precomputed channel-dependent tables (scratch; __device__ globals allowed)
__device__ float g_A2[CCH * NI * NI * NI];  // [c][x][y][i], 1 MB
__device__ float g_c1[CCH * NI * NI];       // [c][x][y]
__device__ float g_c0[CCH * NI];            // [c][x]

typedef unsigned long long ull;

__device__ __forceinline__ ull pack2(float lo, float hi) {
    ull r; asm("mov.b64 %0,{%1,%2};" : "=l"(r) : "f"(lo), "f"(hi)); return r;
}
__device__ __forceinline__ ull dup2(float v) { return pack2(v, v); }
__device__ __forceinline__ void unpack2(ull v, float& lo, float& hi) {
    asm("mov.b64 {%0,%1},%2;" : "=f"(lo), "=f"(hi) : "l"(v));
}
// Packed dual fp32 FMA (sm_100+), only reachable via PTX fma.rn.f32x2
__device__ __forceinline__ ull fma2(ull a, ull b, ull c) {
    ull d; asm("fma.rn.f32x2 %0,%1,%2,%3;" : "=l"(d) : "l"(a), "l"(b), "l"(c)); return d;
}
__device__ __forceinline__ ull add2(ull a, ull b) {
    ull d; asm("add.rn.f32x2 %0,%1,%2;" : "=l"(d) : "l"(a), "l"(b)); return d;
}

// ---------------------------------------------------------------------------
// Precompute A2 = U2(4096x120) @ w2(120x64) as an smem-tiled GEMM.
// grid = 64 blocks (each owns 64 j-rows), 256 threads, 4x4 register tiles.
// Block 0 threads additionally handle the tiny c1 / c0 tables.
// ---------------------------------------------------------------------------
#define TJ 64
#define USTRIDE 124   // padded row stride for sU (kills tj 2-way conflict)

__global__ __launch_bounds__(256)
void precompute_kernel(const float* __restrict__ U2,
                       const float* __restrict__ U1,
                       const float* __restrict__ U0,
                       const float* __restrict__ w2,
                       const float* __restrict__ w1,
                       const float* __restrict__ w0) {
    const int tid = threadIdx.x;
    const int jt  = blockIdx.x;          // j-tile index (0..63)

    __shared__ float sU[TJ * USTRIDE];   // 64 x 120 (padded)  ~31 KB
    __shared__ float sW[NK2 * CCH];      // 120 x 64           30 KB

    // Cooperative, coalesced loads. U2 tile rows are contiguous in global.
    const float* u2g = U2 + (size_t)jt * TJ * NK2;
    for (int i = tid; i < TJ * NK2; i += 256) {
        int j = i / NK2, k = i % NK2;
        sU[j * USTRIDE + k] = u2g[i];
    }
    for (int i = tid; i < NK2 * CCH; i += 256) sW[i] = w2[i];
    __syncthreads();

    // Thread -> (4 c) x (4 j) tile: tc = tid%16 (c-group), tj = tid/16 (j-group)
    const int tc = tid & 15;
    const int tj = tid >> 4;
    const int c0 = tc * 4;
    const int j0 = tj * 4;

    float acc[4][4];
    #pragma unroll
    for (int a = 0; a < 4; a++)
        #pragma unroll
        for (int b = 0; b < 4; b++) acc[a][b] = 0.f;

    #pragma unroll 4
    for (int k = 0; k < NK2; k++) {
        float4 wv = *(const float4*)&sW[k * CCH + c0];
        float u0 = sU[(j0 + 0) * USTRIDE + k];
        float u1 = sU[(j0 + 1) * USTRIDE + k];
        float u2v = sU[(j0 + 2) * USTRIDE + k];
        float u3 = sU[(j0 + 3) * USTRIDE + k];
        acc[0][0] += u0 * wv.x; acc[0][1] += u0 * wv.y; acc[0][2] += u0 * wv.z; acc[0][3] += u0 * wv.w;
        acc[1][0] += u1 * wv.x; acc[1][1] += u1 * wv.y; acc[1][2] += u1 * wv.z; acc[1][3] += u1 * wv.w;
        acc[2][0] += u2v * wv.x; acc[2][1] += u2v * wv.y; acc[2][2] += u2v * wv.z; acc[2][3] += u2v * wv.w;
        acc[3][0] += u3 * wv.x; acc[3][1] += u3 * wv.y; acc[3][2] += u3 * wv.z; acc[3][3] += u3 * wv.w;
    }

    // Store: g_A2[c][j] with j = jt*64 + j0 + a
    #pragma unroll
    for (int a = 0; a < 4; a++) {
        int j = jt * TJ + j0 + a;
        #pragma unroll
        for (int b = 0; b < 4; b++)
            g_A2[(size_t)(c0 + b) * (NI * NI * NI) + j] = acc[a][b];
    }

    // Tiny tables from block 0 (L2-resident inputs, negligible work)
    if (jt == 0) {
        for (int idx = tid; idx < CCH * NI * NI; idx += 256) {
            int c = idx & 63, xy = idx >> 6;
            float s = 0.f;
            #pragma unroll
            for (int k = 0; k < NK1; k++) s += U1[xy * NK1 + k] * w1[k * CCH + c];
            g_c1[c * (NI * NI) + xy] = s;
        }
        for (int idx = tid; idx < CCH * NI; idx += 256) {
            int c = idx & 63, x = idx >> 6;
            float s = 0.f;
            #pragma unroll
            for (int k = 0; k < NK0; k++) s += U0[x * NK0 + k] * w0[k * CCH + c];
            g_c0[c * NI + x] = s;
        }
    }
}

// ---------------------------------------------------------------------------
// Main contraction. Block = (channel c, tile of 512 atoms), 128 threads.
// Each thread processes FOUR atoms: two f32x2 pairs sharing each A2 load.
// A2 in shared memory duplicated into both f32x2 halves (LDS.128 -> two
// ready packed multipliers, broadcast = conflict-free).
// ---------------------------------------------------------------------------
__global__ __launch_bounds__(128)
void contract_kernel(const float* __restrict__ feats,
                     float* __restrict__ out,
                     int Natoms) {
    const int c = blockIdx.y;
    const int tid = threadIdx.x;

    __shared__ __align__(16) ull sA2[NI * NI * NI];  // 32 KB (duplicated pairs)
    __shared__ float sc1[NI * NI];
    __shared__ float sc0[NI];

    {
        const float* a2g = g_A2 + (size_t)c * (NI * NI * NI);
        for (int j = tid; j < NI * NI * NI; j += 128) sA2[j] = dup2(a2g[j]);
        for (int j = tid; j < NI * NI; j += 128) sc1[j] = g_c1[c * (NI * NI) + j];
        if (tid < NI) sc0[tid] = g_c0[c * NI + tid];
    }
    __syncthreads();

    const int base = blockIdx.x * 512 + tid;
    const int n0 = base, n1 = base + 128, n2 = base + 256, n3 = base + 384;
    const bool v0 = n0 < Natoms, v1 = n1 < Natoms, v2 = n2 < Natoms, v3 = n3 < Natoms;

    // Load features for 4 atoms (16 contiguous floats each)
    float4 fa[4], fb[4], fc[4], fd[4];
    {
        const float4* p0 = (const float4*)(feats + ((size_t)n0 * CCH + c) * NI);
        const float4* p1 = (const float4*)(feats + ((size_t)n1 * CCH + c) * NI);
        const float4* p2 = (const float4*)(feats + ((size_t)n2 * CCH + c) * NI);
        const float4* p3 = (const float4*)(feats + ((size_t)n3 * CCH + c) * NI);
        #pragma unroll
        for (int t = 0; t < 4; t++) {
            fa[t] = v0 ? p0[t] : make_float4(0.f, 0.f, 0.f, 0.f);
            fb[t] = v1 ? p1[t] : make_float4(0.f, 0.f, 0.f, 0.f);
            fc[t] = v2 ? p2[t] : make_float4(0.f, 0.f, 0.f, 0.f);
            fd[t] = v3 ? p3[t] : make_float4(0.f, 0.f, 0.f, 0.f);
        }
    }
    ull fp0[NI], fp1[NI];   // packed (atom0,atom1) and (atom2,atom3)
    #pragma unroll
    for (int t = 0; t < 4; t++) {
        fp0[4 * t + 0] = pack2(fa[t].x, fb[t].x);
        fp0[4 * t + 1] = pack2(fa[t].y, fb[t].y);
        fp0[4 * t + 2] = pack2(fa[t].z, fb[t].z);
        fp0[4 * t + 3] = pack2(fa[t].w, fb[t].w);
        fp1[4 * t + 0] = pack2(fc[t].x, fd[t].x);
        fp1[4 * t + 1] = pack2(fc[t].y, fd[t].y);
        fp1[4 * t + 2] = pack2(fc[t].z, fd[t].z);
        fp1[4 * t + 3] = pack2(fc[t].w, fd[t].w);
    }

    const ull z = pack2(0.f, 0.f);
    ull acc0 = z, acc1 = z;

    #pragma unroll 1
    for (int x = 0; x < NI; x++) {
        ull vx0 = z, vx1 = z;
        const ull* rowbase = sA2 + x * (NI * NI);
        const float* c1row = sc1 + x * NI;
        #pragma unroll
        for (int y = 0; y < NI; y++) {
            // m = c1[c,x,y] + sum_i A2[c,x,y,i]*f_i  (4 atoms, 2 packed pairs,
            // even/odd-split accumulators -> 4 independent FMA chains)
            ull c1v = dup2(c1row[y]);
            ull m0a = c1v, m0b = z, m1a = c1v, m1b = z;
            const ulonglong2* r = (const ulonglong2*)(rowbase + y * NI);
            #pragma unroll
            for (int t = 0; t < 8; t++) {
                ulonglong2 p = r[t];            // LDS.128: two duplicated A2 pairs
                m0a = fma2(p.x, fp0[2 * t + 0], m0a);
                m0b = fma2(p.y, fp0[2 * t + 1], m0b);
                m1a = fma2(p.x, fp1[2 * t + 0], m1a);
                m1b = fma2(p.y, fp1[2 * t + 1], m1b);
            }
            vx0 = fma2(add2(m0a, m0b), fp0[y], vx0);   // v[x] += (c1+M)*f_y
            vx1 = fma2(add2(m1a, m1b), fp1[y], vx1);
        }
        ull c0v = dup2(sc0[x]);
        acc0 = fma2(add2(vx0, c0v), fp0[x], acc0);     // out += (c0+v)*f_x
        acc1 = fma2(add2(vx1, c0v), fp1[x], acc1);
    }

    float r0, r1, r2, r3;
    unpack2(acc0, r0, r1);
    unpack2(acc1, r2, r3);
    if (v0) out[(size_t)n0 * CCH + c] = r0;
    if (v1) out[(size_t)n1 * CCH + c] = r1;
    if (v2) out[(size_t)n2 * CCH + c] = r2;
    if (v3) out[(size_t)n3 * CCH + c] = r3;
}

extern "C" void kernel_launch(void* const* d_in, const int* in_sizes, int n_in,
                              void* d_out, int out_size) {
    const float* feats = (const float*)d_in[0];  // [N, C, I]
    const float* U2    = (const float*)d_in[1];  // [I, I, I, K2]
    const float* U1    = (const float*)d_in[2];  // [I, I, K1]
    const float* U0    = (const float*)d_in[3];  // [I, K0]
    const float* w2    = (const float*)d_in[4];  // [K2, C]
    const float* w1    = (const float*)d_in[5];  // [K1, C]
    const float* w0    = (const float*)d_in[6];  // [K0, C]
    float* out = (float*)d_out;                  // [N, C]

    const int Natoms = in_sizes[0] / (CCH * NI);

    precompute_kernel<<<64, 256>>>(U2, U1, U0, w2, w1, w0);

    dim3 grid((Natoms + 511) / 512, CCH);
    contract_kernel<<<grid, 128>>>(feats, out, Natoms);
}

// round 5
// speedup vs baseline: 2.8836x; 1.6776x over previous
#include <cuda_runtime.h>

// Problem constants
#define CCH 64      // channels
#define NI  16      // irreps
#define NK2 120
#define NK1 8
#define NK0 4

#define NPAIR 136        // #(x<=y) pairs
#define RUN_TOTAL 888    // sum over pairs of padded run lengths Lp(y)=((16-y)+1)&~1

// Scratch (__device__ globals; no allocation)
__device__ float g_Usym[RUN_TOTAL * NK2];   // symmetrized U2, padded runs (427 KB)
__device__ float g_U1s[NPAIR * NK1];        // symmetrized U1
__device__ float g_At[CCH * RUN_TOTAL];     // [c][row] cubic table (227 KB)
__device__ float g_c1s[CCH * NPAIR];        // [c][pair]
__device__ float g_c0s[CCH * NI];           // [c][x]

typedef unsigned long long ull;

__device__ __forceinline__ ull pack2(float lo, float hi) {
    ull r; asm("mov.b64 %0,{%1,%2};" : "=l"(r) : "f"(lo), "f"(hi)); return r;
}
__device__ __forceinline__ ull dup2(float v) { return pack2(v, v); }
__device__ __forceinline__ void unpack2(ull v, float& lo, float& hi) {
    asm("mov.b64 {%0,%1},%2;" : "=f"(lo), "=f"(hi) : "l"(v));
}
__device__ __forceinline__ ull fma2(ull a, ull b, ull c) {
    ull d; asm("fma.rn.f32x2 %0,%1,%2,%3;" : "=l"(d) : "l"(a), "l"(b), "l"(c)); return d;
}
__device__ __forceinline__ ull add2(ull a, ull b) {
    ull d; asm("add.rn.f32x2 %0,%1,%2;" : "=l"(d) : "l"(a), "l"(b)); return d;
}
__device__ __forceinline__ ull mul2(ull a, ull b) {
    ull d; asm("mul.rn.f32x2 %0,%1,%2;" : "=l"(d) : "l"(a), "l"(b)); return d;
}

// Sum of U2 over DISTINCT index-permutations of the multiset {x,y,i}, at basis k.
__device__ __forceinline__ float sym_sum_U2(const float* __restrict__ U2,
                                            int x, int y, int i, int k) {
    int ta[6] = {x, x, y, y, i, i};
    int tb[6] = {y, i, x, i, x, y};
    int tc[6] = {i, y, i, x, y, x};
    int seen[6]; int ns = 0;
    float v = 0.f;
    for (int q = 0; q < 6; q++) {
        int code = (ta[q] << 8) | (tb[q] << 4) | tc[q];
        bool dup = false;
        for (int s = 0; s < ns; s++) if (seen[s] == code) dup = true;
        if (!dup) {
            seen[ns++] = code;
            v += U2[(((ta[q] * NI + tb[q]) * NI) + tc[q]) * NK2 + k];
        }
    }
    return v;
}

// ---------------------------------------------------------------------------
// Kernel A: symmetrize U2 (per sorted triple, padded runs) and U1.
// grid = NPAIR+1 blocks, 120 threads.
// ---------------------------------------------------------------------------
__global__ void sym_kernel(const float* __restrict__ U2,
                           const float* __restrict__ U1) {
    int p = blockIdx.x;
    if (p < NPAIR) {
        // decode pair ordinal p = y(y+1)/2 + x, x<=y
        int y = 0;
        while ((y + 1) * (y + 2) / 2 <= p) y++;
        int x = p - y * (y + 1) / 2;
        int L = NI - y, Lp = (L + 1) & ~1, i0 = NI - Lp;
        int base = 0;
        for (int yy = 0; yy < y; yy++) base += (yy + 1) * (((NI - yy) + 1) & ~1);
        int roff = base + x * Lp;
        int k = threadIdx.x;                      // 0..119
        for (int j = 0; j < Lp; j++) {
            int i = i0 + j;
            float v = (i >= y) ? sym_sum_U2(U2, x, y, i, k) : 0.f;
            g_Usym[(roff + j) * NK2 + k] = v;
        }
    } else {
        // U1 symmetrization: pair (x<=y): U1[x,y,:] (+ U1[y,x,:] if x!=y)
        for (int idx = threadIdx.x; idx < NPAIR * NK1; idx += 120) {
            int pp = idx / NK1, k = idx % NK1;
            int y = 0;
            while ((y + 1) * (y + 2) / 2 <= pp) y++;
            int x = pp - y * (y + 1) / 2;
            float v = U1[(x * NI + y) * NK1 + k];
            if (x != y) v += U1[(y * NI + x) * NK1 + k];
            g_U1s[idx] = v;
        }
    }
}

// ---------------------------------------------------------------------------
// Kernel B: At = Usym(888x120) @ w2(120x64); plus tiny c1s / c0s tables.
// Blocks 0..221: 4 rows x 64 channels each. Block 222: c1s + c0s.
// ---------------------------------------------------------------------------
__global__ __launch_bounds__(256)
void gemm_kernel(const float* __restrict__ w2,
                 const float* __restrict__ w1,
                 const float* __restrict__ w0,
                 const float* __restrict__ U0) {
    const int bid = blockIdx.x, tid = threadIdx.x;
    if (bid < 222) {
        __shared__ float sW[NK2 * CCH];   // 30 KB
        __shared__ float sU[4 * NK2];
        for (int i = tid; i < NK2 * CCH; i += 256) sW[i] = w2[i];
        int r0 = bid * 4;
        for (int i = tid; i < 4 * NK2; i += 256) {
            int rr = r0 + i / NK2;
            sU[i] = (rr < RUN_TOTAL) ? g_Usym[rr * NK2 + (i % NK2)] : 0.f;
        }
        __syncthreads();
        int tr = tid >> 6, c = tid & 63;
        int row = r0 + tr;
        float acc = 0.f;
        #pragma unroll 8
        for (int k = 0; k < NK2; k++) acc += sU[tr * NK2 + k] * sW[k * CCH + c];
        if (row < RUN_TOTAL) g_At[c * RUN_TOTAL + row] = acc;
    } else {
        for (int idx = tid; idx < CCH * NPAIR; idx += 256) {
            int c = idx & 63, p = idx >> 6;
            float s = 0.f;
            #pragma unroll
            for (int k = 0; k < NK1; k++) s += g_U1s[p * NK1 + k] * w1[k * CCH + c];
            g_c1s[c * NPAIR + p] = s;
        }
        for (int idx = tid; idx < CCH * NI; idx += 256) {
            int c = idx & 63, x = idx >> 6;
            float s = 0.f;
            #pragma unroll
            for (int k = 0; k < NK0; k++) s += U0[x * NK0 + k] * w0[k * CCH + c];
            g_c0s[c * NI + x] = s;
        }
    }
}

// ---------------------------------------------------------------------------
// Contract kernel (symmetrized). Block = (channel c, tile of 1024 atoms),
// 256 threads, 4 atoms/thread as two f32x2 pairs sharing every smem load.
//   out = sum_x c0_x f_x + sum_{x<=y} c1s f_x f_y + sum_{x<=y<=i} At f_x f_y f_i
// At runs per pair are front-zero-padded to even length so LDS.128 stays
// aligned and the i index never leaves [0,16).
// ---------------------------------------------------------------------------
__global__ __launch_bounds__(256, 2)
void contract_kernel(const float* __restrict__ feats,
                     float* __restrict__ out,
                     int Natoms) {
    const int c = blockIdx.y;
    const int tid = threadIdx.x;

    __shared__ __align__(16) ull sA[RUN_TOTAL];   // dup'd cubic table, ~7 KB
    __shared__ ull sC1[NPAIR];                    // dup'd
    __shared__ ull sC0[NI];                       // dup'd

    {
        const float* at = g_At + (size_t)c * RUN_TOTAL;
        for (int j = tid; j < RUN_TOTAL; j += 256) sA[j] = dup2(at[j]);
        for (int j = tid; j < NPAIR; j += 256) sC1[j] = dup2(g_c1s[c * NPAIR + j]);
        if (tid < NI) sC0[tid] = dup2(g_c0s[c * NI + tid]);
    }
    __syncthreads();

    const int base = blockIdx.x * 1024 + tid;
    const int n0 = base, n1 = base + 256, n2 = base + 512, n3 = base + 768;
    const bool v0 = n0 < Natoms, v1 = n1 < Natoms, v2 = n2 < Natoms, v3 = n3 < Natoms;

    float4 fa[4], fb[4], fc[4], fd[4];
    {
        const float4* p0 = (const float4*)(feats + ((size_t)n0 * CCH + c) * NI);
        const float4* p1 = (const float4*)(feats + ((size_t)n1 * CCH + c) * NI);
        const float4* p2 = (const float4*)(feats + ((size_t)n2 * CCH + c) * NI);
        const float4* p3 = (const float4*)(feats + ((size_t)n3 * CCH + c) * NI);
        #pragma unroll
        for (int t = 0; t < 4; t++) {
            fa[t] = v0 ? p0[t] : make_float4(0.f, 0.f, 0.f, 0.f);
            fb[t] = v1 ? p1[t] : make_float4(0.f, 0.f, 0.f, 0.f);
            fc[t] = v2 ? p2[t] : make_float4(0.f, 0.f, 0.f, 0.f);
            fd[t] = v3 ? p3[t] : make_float4(0.f, 0.f, 0.f, 0.f);
        }
    }
    ull fp0[NI], fp1[NI];
    #pragma unroll
    for (int t = 0; t < 4; t++) {
        fp0[4 * t + 0] = pack2(fa[t].x, fb[t].x);
        fp0[4 * t + 1] = pack2(fa[t].y, fb[t].y);
        fp0[4 * t + 2] = pack2(fa[t].z, fb[t].z);
        fp0[4 * t + 3] = pack2(fa[t].w, fb[t].w);
        fp1[4 * t + 0] = pack2(fc[t].x, fd[t].x);
        fp1[4 * t + 1] = pack2(fc[t].y, fd[t].y);
        fp1[4 * t + 2] = pack2(fc[t].z, fd[t].z);
        fp1[4 * t + 3] = pack2(fc[t].w, fd[t].w);
    }

    const ull z = pack2(0.f, 0.f);
    ull acc0 = z, acc1 = z;

    // linear term
    #pragma unroll
    for (int x = 0; x < NI; x++) {
        ull c0v = sC0[x];
        acc0 = fma2(c0v, fp0[x], acc0);
        acc1 = fma2(c0v, fp1[x], acc1);
    }

    // quadratic + cubic, fully unrolled (all offsets compile-time)
    int roff = 0, pp = 0;
    #pragma unroll
    for (int y = 0; y < NI; y++) {
        const int L = NI - y;
        const int Lp = (L + 1) & ~1;
        const int i0 = NI - Lp;
        #pragma unroll
        for (int x = 0; x <= y; x++) {
            ull c1v = sC1[pp];
            ull s0a = c1v, s0b = z, s1a = c1v, s1b = z;
            const ulonglong2* r = (const ulonglong2*)(sA + roff);
            #pragma unroll
            for (int t = 0; t < Lp / 2; t++) {
                ulonglong2 pv = r[t];
                s0a = fma2(pv.x, fp0[i0 + 2 * t + 0], s0a);
                s0b = fma2(pv.y, fp0[i0 + 2 * t + 1], s0b);
                s1a = fma2(pv.x, fp1[i0 + 2 * t + 0], s1a);
                s1b = fma2(pv.y, fp1[i0 + 2 * t + 1], s1b);
            }
            ull P0 = mul2(fp0[x], fp0[y]);
            ull P1 = mul2(fp1[x], fp1[y]);
            acc0 = fma2(add2(s0a, s0b), P0, acc0);
            acc1 = fma2(add2(s1a, s1b), P1, acc1);
            roff += Lp; pp++;
        }
    }

    float r0, r1, r2, r3;
    unpack2(acc0, r0, r1);
    unpack2(acc1, r2, r3);
    if (v0) out[(size_t)n0 * CCH + c] = r0;
    if (v1) out[(size_t)n1 * CCH + c] = r1;
    if (v2) out[(size_t)n2 * CCH + c] = r2;
    if (v3) out[(size_t)n3 * CCH + c] = r3;
}

extern "C" void kernel_launch(void* const* d_in, const int* in_sizes, int n_in,
                              void* d_out, int out_size) {
    const float* feats = (const float*)d_in[0];  // [N, C, I]
    const float* U2    = (const float*)d_in[1];  // [I, I, I, K2]
    const float* U1    = (const float*)d_in[2];  // [I, I, K1]
    const float* U0    = (const float*)d_in[3];  // [I, K0]
    const float* w2    = (const float*)d_in[4];  // [K2, C]
    const float* w1    = (const float*)d_in[5];  // [K1, C]
    const float* w0    = (const float*)d_in[6];  // [K0, C]
    float* out = (float*)d_out;                  // [N, C]

    const int Natoms = in_sizes[0] / (CCH * NI);

    sym_kernel<<<NPAIR + 1, 120>>>(U2, U1);
    gemm_kernel<<<223, 256>>>(w2, w1, w0, U0);

    dim3 grid((Natoms + 1023) / 1024, CCH);
    contract_kernel<<<grid, 256>>>(feats, out, Natoms);
}

// round 6
// speedup vs baseline: 3.3338x; 1.1561x over previous
#include <cuda_runtime.h>

// Problem constants
#define CCH 64      // channels
#define NI  16      // irreps
#define NK2 120
#define NK1 8
#define NK0 4

#define NPAIR 136        // #(x<=y) pairs
#define RUN_TOTAL 888    // sum over pairs of padded run lengths Lp(y)=((16-y)+1)&~1

// Scratch (__device__ globals; no allocation)
__device__ float g_Usym[RUN_TOTAL * NK2];   // symmetrized U2, padded runs
__device__ float g_U1s[NPAIR * NK1];        // symmetrized U1
__device__ float g_At[CCH * RUN_TOTAL];     // [c][row] cubic table
__device__ float g_c1s[CCH * NPAIR];        // [c][pair]
__device__ float g_c0s[CCH * NI];           // [c][x]
__device__ unsigned int g_item;             // work-queue counter (reset each launch)

typedef unsigned long long ull;

__device__ __forceinline__ ull pack2(float lo, float hi) {
    ull r; asm("mov.b64 %0,{%1,%2};" : "=l"(r) : "f"(lo), "f"(hi)); return r;
}
__device__ __forceinline__ ull dup2(float v) { return pack2(v, v); }
__device__ __forceinline__ void unpack2(ull v, float& lo, float& hi) {
    asm("mov.b64 {%0,%1},%2;" : "=f"(lo), "=f"(hi) : "l"(v));
}
__device__ __forceinline__ ull fma2(ull a, ull b, ull c) {
    ull d; asm("fma.rn.f32x2 %0,%1,%2,%3;" : "=l"(d) : "l"(a), "l"(b), "l"(c)); return d;
}
__device__ __forceinline__ ull add2(ull a, ull b) {
    ull d; asm("add.rn.f32x2 %0,%1,%2;" : "=l"(d) : "l"(a), "l"(b)); return d;
}
__device__ __forceinline__ ull mul2(ull a, ull b) {
    ull d; asm("mul.rn.f32x2 %0,%1,%2;" : "=l"(d) : "l"(a), "l"(b)); return d;
}

// Sum of U2 over DISTINCT index-permutations of the multiset {x,y,i}, at basis k.
__device__ __forceinline__ float sym_sum_U2(const float* __restrict__ U2,
                                            int x, int y, int i, int k) {
    int ta[6] = {x, x, y, y, i, i};
    int tb[6] = {y, i, x, i, x, y};
    int tc[6] = {i, y, i, x, y, x};
    int seen[6]; int ns = 0;
    float v = 0.f;
    #pragma unroll
    for (int q = 0; q < 6; q++) {
        int code = (ta[q] << 8) | (tb[q] << 4) | tc[q];
        bool dup = false;
        for (int s = 0; s < ns; s++) if (seen[s] == code) dup = true;
        if (!dup) {
            seen[ns++] = code;
            v += U2[(((ta[q] * NI + tb[q]) * NI) + tc[q]) * NK2 + k];
        }
    }
    return v;
}

// ---------------------------------------------------------------------------
// Kernel A: symmetrize U2 and U1 — one thread per OUTPUT element.
// 106560 Usym elements + 1088 U1s elements. Grid 421 x 256.
// Each thread: <=6 independent gathers, 1 store. Latency fully overlapped.
// ---------------------------------------------------------------------------
__global__ __launch_bounds__(256)
void sym_kernel(const float* __restrict__ U2,
                const float* __restrict__ U1) {
    const int idx = blockIdx.x * 256 + threadIdx.x;
    if (idx < RUN_TOTAL * NK2) {
        const int row = idx / NK2;
        const int k   = idx % NK2;
        // decode row -> (x, y, j)
        int y = 0, base = 0, Lp = 0;
        for (;;) {
            Lp = ((NI - y) + 1) & ~1;
            int sz = (y + 1) * Lp;
            if (row < base + sz) break;
            base += sz; y++;
        }
        int rem = row - base;
        int x = rem / Lp;
        int j = rem - x * Lp;
        int i = (NI - Lp) + j;
        float v = (i >= y) ? sym_sum_U2(U2, x, y, i, k) : 0.f;
        g_Usym[row * NK2 + k] = v;
    } else {
        int idx2 = idx - RUN_TOTAL * NK2;
        if (idx2 < NPAIR * NK1) {
            int p = idx2 / NK1, k = idx2 - (idx2 / NK1) * NK1;
            int y = 0;
            while ((y + 1) * (y + 2) / 2 <= p) y++;
            int x = p - y * (y + 1) / 2;
            float v = U1[(x * NI + y) * NK1 + k];
            if (x != y) v += U1[(y * NI + x) * NK1 + k];
            g_U1s[idx2] = v;
        }
    }
}

// ---------------------------------------------------------------------------
// Kernel B: At = Usym(888x120) @ w2(120x64); c1s / c0s; work-counter reset.
// Blocks 0..55: 16 rows x 64 channels, 4 interleaved accumulators/thread.
// Block 56: tiny tables + g_item = 0.
// ---------------------------------------------------------------------------
__global__ __launch_bounds__(256)
void gemm_kernel(const float* __restrict__ w2,
                 const float* __restrict__ w1,
                 const float* __restrict__ w0,
                 const float* __restrict__ U0) {
    const int bid = blockIdx.x, tid = threadIdx.x;
    if (bid < 56) {
        __shared__ float sW[NK2 * CCH];      // 30 KB
        __shared__ float sU[16 * NK2];       // 7.5 KB
        const int r0 = bid * 16;
        for (int i = tid; i < NK2 * CCH; i += 256) sW[i] = w2[i];
        for (int i = tid; i < 16 * NK2; i += 256) {
            int rr = r0 + i / NK2;
            sU[i] = (rr < RUN_TOTAL) ? g_Usym[rr * NK2 + (i % NK2)] : 0.f;
        }
        __syncthreads();
        const int c = tid & 63;
        const int tr = tid >> 6;             // 0..3
        float acc[4] = {0.f, 0.f, 0.f, 0.f};
        #pragma unroll 4
        for (int k = 0; k < NK2; k++) {
            float wv = sW[k * CCH + c];
            #pragma unroll
            for (int q = 0; q < 4; q++)
                acc[q] += sU[(tr + 4 * q) * NK2 + k] * wv;   // sU broadcast per warp
        }
        #pragma unroll
        for (int q = 0; q < 4; q++) {
            int row = r0 + tr + 4 * q;
            if (row < RUN_TOTAL) g_At[c * RUN_TOTAL + row] = acc[q];
        }
    } else {
        for (int idx = tid; idx < CCH * NPAIR; idx += 256) {
            int c = idx & 63, p = idx >> 6;
            float s = 0.f;
            #pragma unroll
            for (int k = 0; k < NK1; k++) s += g_U1s[p * NK1 + k] * w1[k * CCH + c];
            g_c1s[c * NPAIR + p] = s;
        }
        for (int idx = tid; idx < CCH * NI; idx += 256) {
            int c = idx & 63, x = idx >> 6;
            float s = 0.f;
            #pragma unroll
            for (int k = 0; k < NK0; k++) s += U0[x * NK0 + k] * w0[k * CCH + c];
            g_c0s[c * NI + x] = s;
        }
        if (tid == 0) g_item = 0u;           // reset work queue (every replay)
    }
}

// ---------------------------------------------------------------------------
// Contract kernel: persistent CTAs popping (channel, 1024-atom tile) items
// from a global atomic queue (perfect load balance, deterministic output).
// 256 threads, 4 atoms/thread as two f32x2 pairs sharing every smem load.
//   out = sum_x c0_x f_x + sum_{x<=y} c1s f_x f_y + sum_{x<=y<=i} At f_x f_y f_i
// ---------------------------------------------------------------------------
__global__ __launch_bounds__(256, 2)
void contract_kernel(const float* __restrict__ feats,
                     float* __restrict__ out,
                     int Natoms, int nItems) {
    const int tid = threadIdx.x;

    __shared__ __align__(16) ull sA[RUN_TOTAL];   // dup'd cubic table ~7 KB
    __shared__ ull sC1[NPAIR];
    __shared__ ull sC0[NI];
    __shared__ unsigned int s_item;

    const ull z = pack2(0.f, 0.f);

    for (;;) {
        if (tid == 0) s_item = atomicAdd(&g_item, 1u);
        __syncthreads();                      // publish s_item; prior sA reads done
        const unsigned int item = s_item;
        if (item >= (unsigned int)nItems) break;
        const int c    = item & 63;
        const int tile = item >> 6;

        {
            const float* at = g_At + (size_t)c * RUN_TOTAL;
            for (int j = tid; j < RUN_TOTAL; j += 256) sA[j] = dup2(at[j]);
            for (int j = tid; j < NPAIR; j += 256) sC1[j] = dup2(g_c1s[c * NPAIR + j]);
            if (tid < NI) sC0[tid] = dup2(g_c0s[c * NI + tid]);
        }
        __syncthreads();

        const int base = tile * 1024 + tid;
        const int n0 = base, n1 = base + 256, n2 = base + 512, n3 = base + 768;
        const bool v0 = n0 < Natoms, v1 = n1 < Natoms, v2 = n2 < Natoms, v3 = n3 < Natoms;

        float4 fa[4], fb[4], fc[4], fd[4];
        {
            const float4* p0 = (const float4*)(feats + ((size_t)n0 * CCH + c) * NI);
            const float4* p1 = (const float4*)(feats + ((size_t)n1 * CCH + c) * NI);
            const float4* p2 = (const float4*)(feats + ((size_t)n2 * CCH + c) * NI);
            const float4* p3 = (const float4*)(feats + ((size_t)n3 * CCH + c) * NI);
            #pragma unroll
            for (int t = 0; t < 4; t++) {
                fa[t] = v0 ? p0[t] : make_float4(0.f, 0.f, 0.f, 0.f);
                fb[t] = v1 ? p1[t] : make_float4(0.f, 0.f, 0.f, 0.f);
                fc[t] = v2 ? p2[t] : make_float4(0.f, 0.f, 0.f, 0.f);
                fd[t] = v3 ? p3[t] : make_float4(0.f, 0.f, 0.f, 0.f);
            }
        }
        ull fp0[NI], fp1[NI];
        #pragma unroll
        for (int t = 0; t < 4; t++) {
            fp0[4 * t + 0] = pack2(fa[t].x, fb[t].x);
            fp0[4 * t + 1] = pack2(fa[t].y, fb[t].y);
            fp0[4 * t + 2] = pack2(fa[t].z, fb[t].z);
            fp0[4 * t + 3] = pack2(fa[t].w, fb[t].w);
            fp1[4 * t + 0] = pack2(fc[t].x, fd[t].x);
            fp1[4 * t + 1] = pack2(fc[t].y, fd[t].y);
            fp1[4 * t + 2] = pack2(fc[t].z, fd[t].z);
            fp1[4 * t + 3] = pack2(fc[t].w, fd[t].w);
        }

        ull acc0 = z, acc1 = z;

        // linear term
        #pragma unroll
        for (int x = 0; x < NI; x++) {
            ull c0v = sC0[x];
            acc0 = fma2(c0v, fp0[x], acc0);
            acc1 = fma2(c0v, fp1[x], acc1);
        }

        // quadratic + cubic, fully unrolled (all offsets compile-time)
        int roff = 0, pp = 0;
        #pragma unroll
        for (int y = 0; y < NI; y++) {
            const int L = NI - y;
            const int Lp = (L + 1) & ~1;
            const int i0 = NI - Lp;
            #pragma unroll
            for (int x = 0; x <= y; x++) {
                ull c1v = sC1[pp];
                ull s0a = c1v, s0b = z, s1a = c1v, s1b = z;
                const ulonglong2* r = (const ulonglong2*)(sA + roff);
                #pragma unroll
                for (int t = 0; t < Lp / 2; t++) {
                    ulonglong2 pv = r[t];
                    s0a = fma2(pv.x, fp0[i0 + 2 * t + 0], s0a);
                    s0b = fma2(pv.y, fp0[i0 + 2 * t + 1], s0b);
                    s1a = fma2(pv.x, fp1[i0 + 2 * t + 0], s1a);
                    s1b = fma2(pv.y, fp1[i0 + 2 * t + 1], s1b);
                }
                ull P0 = mul2(fp0[x], fp0[y]);
                ull P1 = mul2(fp1[x], fp1[y]);
                acc0 = fma2(add2(s0a, s0b), P0, acc0);
                acc1 = fma2(add2(s1a, s1b), P1, acc1);
                roff += Lp; pp++;
            }
        }

        float r0, r1, r2, r3;
        unpack2(acc0, r0, r1);
        unpack2(acc1, r2, r3);
        if (v0) out[(size_t)n0 * CCH + c] = r0;
        if (v1) out[(size_t)n1 * CCH + c] = r1;
        if (v2) out[(size_t)n2 * CCH + c] = r2;
        if (v3) out[(size_t)n3 * CCH + c] = r3;
    }
}

extern "C" void kernel_launch(void* const* d_in, const int* in_sizes, int n_in,
                              void* d_out, int out_size) {
    const float* feats = (const float*)d_in[0];  // [N, C, I]
    const float* U2    = (const float*)d_in[1];  // [I, I, I, K2]
    const float* U1    = (const float*)d_in[2];  // [I, I, K1]
    const float* U0    = (const float*)d_in[3];  // [I, K0]
    const float* w2    = (const float*)d_in[4];  // [K2, C]
    const float* w1    = (const float*)d_in[5];  // [K1, C]
    const float* w0    = (const float*)d_in[6];  // [K0, C]
    float* out = (float*)d_out;                  // [N, C]

    const int Natoms = in_sizes[0] / (CCH * NI);
    const int nTiles = (Natoms + 1023) / 1024;
    const int nItems = nTiles * CCH;

    const int symElems = RUN_TOTAL * NK2 + NPAIR * NK1;
    sym_kernel<<<(symElems + 255) / 256, 256>>>(U2, U1);
    gemm_kernel<<<57, 256>>>(w2, w1, w0, U0);

    contract_kernel<<<304, 256>>>(feats, out, Natoms, nItems);
}

// round 7
// speedup vs baseline: 3.5353x; 1.0605x over previous
#include <cuda_runtime.h>

// Problem constants
#define CCH 64      // channels
#define NI  16      // irreps
#define NK2 120
#define NK1 8
#define NK0 4

#define NPAIR 136        // #(x<=y) pairs
#define RUN_TOTAL 888    // sum over pairs of padded run lengths Lp(y)=((16-y)+1)&~1

// Scratch (__device__ globals; no allocation)
__device__ float g_Usym[RUN_TOTAL * NK2];   // symmetrized U2, padded runs
__device__ float g_U1s[NPAIR * NK1];        // symmetrized U1
__device__ float g_At[CCH * RUN_TOTAL];     // [c][row] cubic table
__device__ float g_c1s[CCH * NPAIR];        // [c][pair]
__device__ float g_c0s[CCH * NI];           // [c][x]
__device__ unsigned int g_item;             // work-queue counter (reset each launch)

typedef unsigned long long ull;

__device__ __forceinline__ ull pack2(float lo, float hi) {
    ull r; asm("mov.b64 %0,{%1,%2};" : "=l"(r) : "f"(lo), "f"(hi)); return r;
}
__device__ __forceinline__ ull dup2(float v) { return pack2(v, v); }
__device__ __forceinline__ void unpack2(ull v, float& lo, float& hi) {
    asm("mov.b64 {%0,%1},%2;" : "=f"(lo), "=f"(hi) : "l"(v));
}
__device__ __forceinline__ ull fma2(ull a, ull b, ull c) {
    ull d; asm("fma.rn.f32x2 %0,%1,%2,%3;" : "=l"(d) : "l"(a), "l"(b), "l"(c)); return d;
}

// Sum of U2 over DISTINCT index-permutations of the multiset {x,y,i}, at basis k.
__device__ __forceinline__ float sym_sum_U2(const float* __restrict__ U2,
                                            int x, int y, int i, int k) {
    int ta[6] = {x, x, y, y, i, i};
    int tb[6] = {y, i, x, i, x, y};
    int tc[6] = {i, y, i, x, y, x};
    int seen[6]; int ns = 0;
    float v = 0.f;
    #pragma unroll
    for (int q = 0; q < 6; q++) {
        int code = (ta[q] << 8) | (tb[q] << 4) | tc[q];
        bool dup = false;
        for (int s = 0; s < ns; s++) if (seen[s] == code) dup = true;
        if (!dup) {
            seen[ns++] = code;
            v += U2[(((ta[q] * NI + tb[q]) * NI) + tc[q]) * NK2 + k];
        }
    }
    return v;
}

// ---------------------------------------------------------------------------
// Kernel A: symmetrize U2 and U1 — one thread per OUTPUT element.
// ---------------------------------------------------------------------------
__global__ __launch_bounds__(256)
void sym_kernel(const float* __restrict__ U2,
                const float* __restrict__ U1) {
    const int idx = blockIdx.x * 256 + threadIdx.x;
    if (idx < RUN_TOTAL * NK2) {
        const int row = idx / NK2;
        const int k   = idx % NK2;
        int y = 0, base = 0, Lp = 0;
        for (;;) {
            Lp = ((NI - y) + 1) & ~1;
            int sz = (y + 1) * Lp;
            if (row < base + sz) break;
            base += sz; y++;
        }
        int rem = row - base;
        int x = rem / Lp;
        int j = rem - x * Lp;
        int i = (NI - Lp) + j;
        float v = (i >= y) ? sym_sum_U2(U2, x, y, i, k) : 0.f;
        g_Usym[row * NK2 + k] = v;
    } else {
        int idx2 = idx - RUN_TOTAL * NK2;
        if (idx2 < NPAIR * NK1) {
            int p = idx2 / NK1, k = idx2 - (idx2 / NK1) * NK1;
            int y = 0;
            while ((y + 1) * (y + 2) / 2 <= p) y++;
            int x = p - y * (y + 1) / 2;
            float v = U1[(x * NI + y) * NK1 + k];
            if (x != y) v += U1[(y * NI + x) * NK1 + k];
            g_U1s[idx2] = v;
        }
    }
}

// ---------------------------------------------------------------------------
// Kernel B: At = Usym(888x120) @ w2(120x64); c1s / c0s; work-counter reset.
// ---------------------------------------------------------------------------
__global__ __launch_bounds__(256)
void gemm_kernel(const float* __restrict__ w2,
                 const float* __restrict__ w1,
                 const float* __restrict__ w0,
                 const float* __restrict__ U0) {
    const int bid = blockIdx.x, tid = threadIdx.x;
    if (bid < 56) {
        __shared__ float sW[NK2 * CCH];      // 30 KB
        __shared__ float sU[16 * NK2];       // 7.5 KB
        const int r0 = bid * 16;
        for (int i = tid; i < NK2 * CCH; i += 256) sW[i] = w2[i];
        for (int i = tid; i < 16 * NK2; i += 256) {
            int rr = r0 + i / NK2;
            sU[i] = (rr < RUN_TOTAL) ? g_Usym[rr * NK2 + (i % NK2)] : 0.f;
        }
        __syncthreads();
        const int c = tid & 63;
        const int tr = tid >> 6;             // 0..3
        float acc[4] = {0.f, 0.f, 0.f, 0.f};
        #pragma unroll 4
        for (int k = 0; k < NK2; k++) {
            float wv = sW[k * CCH + c];
            #pragma unroll
            for (int q = 0; q < 4; q++)
                acc[q] += sU[(tr + 4 * q) * NK2 + k] * wv;
        }
        #pragma unroll
        for (int q = 0; q < 4; q++) {
            int row = r0 + tr + 4 * q;
            if (row < RUN_TOTAL) g_At[c * RUN_TOTAL + row] = acc[q];
        }
    } else {
        for (int idx = tid; idx < CCH * NPAIR; idx += 256) {
            int c = idx & 63, p = idx >> 6;
            float s = 0.f;
            #pragma unroll
            for (int k = 0; k < NK1; k++) s += g_U1s[p * NK1 + k] * w1[k * CCH + c];
            g_c1s[c * NPAIR + p] = s;
        }
        for (int idx = tid; idx < CCH * NI; idx += 256) {
            int c = idx & 63, x = idx >> 6;
            float s = 0.f;
            #pragma unroll
            for (int k = 0; k < NK0; k++) s += U0[x * NK0 + k] * w0[k * CCH + c];
            g_c0s[c * NI + x] = s;
        }
        if (tid == 0) g_item = 0u;           // reset work queue (every replay)
    }
}

// ---------------------------------------------------------------------------
// Contract kernel: persistent CTAs popping (channel, 1024-atom tile) items.
// 256 threads, 4 atoms/thread as two f32x2 pairs sharing every smem load.
// Horner form:  out = sum_y f_y * ( c0_y + sum_{x<=y} f_x * S_xy )
//               S_xy = c1s_xy + sum_i At_xyi f_i
// ---------------------------------------------------------------------------
__global__ __launch_bounds__(256, 2)
void contract_kernel(const float* __restrict__ feats,
                     float* __restrict__ out,
                     int Natoms, int nItems) {
    const int tid = threadIdx.x;

    __shared__ __align__(16) ull sA[RUN_TOTAL];   // dup'd cubic table ~7 KB
    __shared__ ull sC1[NPAIR];
    __shared__ ull sC0[NI];
    __shared__ unsigned int s_item;

    const ull z = pack2(0.f, 0.f);

    for (;;) {
        if (tid == 0) s_item = atomicAdd(&g_item, 1u);
        __syncthreads();                      // publish s_item; prior sA reads done
        const unsigned int item = s_item;
        if (item >= (unsigned int)nItems) break;
        const int c    = item & 63;
        const int tile = item >> 6;

        {
            const float* at = g_At + (size_t)c * RUN_TOTAL;
            for (int j = tid; j < RUN_TOTAL; j += 256) sA[j] = dup2(at[j]);
            for (int j = tid; j < NPAIR; j += 256) sC1[j] = dup2(g_c1s[c * NPAIR + j]);
            if (tid < NI) sC0[tid] = dup2(g_c0s[c * NI + tid]);
        }
        __syncthreads();

        const int base = tile * 1024 + tid;
        const int n0 = base, n1 = base + 256, n2 = base + 512, n3 = base + 768;
        const bool v0 = n0 < Natoms, v1 = n1 < Natoms, v2 = n2 < Natoms, v3 = n3 < Natoms;

        float4 fa[4], fb[4], fc[4], fd[4];
        {
            const float4* p0 = (const float4*)(feats + ((size_t)n0 * CCH + c) * NI);
            const float4* p1 = (const float4*)(feats + ((size_t)n1 * CCH + c) * NI);
            const float4* p2 = (const float4*)(feats + ((size_t)n2 * CCH + c) * NI);
            const float4* p3 = (const float4*)(feats + ((size_t)n3 * CCH + c) * NI);
            #pragma unroll
            for (int t = 0; t < 4; t++) {
                fa[t] = v0 ? p0[t] : make_float4(0.f, 0.f, 0.f, 0.f);
                fb[t] = v1 ? p1[t] : make_float4(0.f, 0.f, 0.f, 0.f);
                fc[t] = v2 ? p2[t] : make_float4(0.f, 0.f, 0.f, 0.f);
                fd[t] = v3 ? p3[t] : make_float4(0.f, 0.f, 0.f, 0.f);
            }
        }
        ull fp0[NI], fp1[NI];
        #pragma unroll
        for (int t = 0; t < 4; t++) {
            fp0[4 * t + 0] = pack2(fa[t].x, fb[t].x);
            fp0[4 * t + 1] = pack2(fa[t].y, fb[t].y);
            fp0[4 * t + 2] = pack2(fa[t].z, fb[t].z);
            fp0[4 * t + 3] = pack2(fa[t].w, fb[t].w);
            fp1[4 * t + 0] = pack2(fc[t].x, fd[t].x);
            fp1[4 * t + 1] = pack2(fc[t].y, fd[t].y);
            fp1[4 * t + 2] = pack2(fc[t].z, fd[t].z);
            fp1[4 * t + 3] = pack2(fc[t].w, fd[t].w);
        }

        ull acc0 = z, acc1 = z;

        int roff = 0, pp = 0;
        #pragma unroll
        for (int y = 0; y < NI; y++) {
            const int L = NI - y;
            const int Lp = (L + 1) & ~1;
            const int i0 = NI - Lp;
            ull t0 = sC0[y];                  // c0 folded into t_y seed
            ull t1 = t0;
            #pragma unroll
            for (int x = 0; x <= y; x++) {
                // S = c1 + sum_i At*f_i  (single chain per atom-pair)
                ull s0 = sC1[pp];
                ull s1 = s0;
                const ulonglong2* r = (const ulonglong2*)(sA + roff);
                #pragma unroll
                for (int t = 0; t < Lp / 2; t++) {
                    ulonglong2 pv = r[t];
                    s0 = fma2(pv.x, fp0[i0 + 2 * t + 0], s0);
                    s0 = fma2(pv.y, fp0[i0 + 2 * t + 1], s0);
                    s1 = fma2(pv.x, fp1[i0 + 2 * t + 0], s1);
                    s1 = fma2(pv.y, fp1[i0 + 2 * t + 1], s1);
                }
                t0 = fma2(s0, fp0[x], t0);    // t_y += S * f_x
                t1 = fma2(s1, fp1[x], t1);
                roff += Lp; pp++;
            }
            acc0 = fma2(t0, fp0[y], acc0);    // out += t_y * f_y
            acc1 = fma2(t1, fp1[y], acc1);
        }

        float r0, r1, r2, r3;
        unpack2(acc0, r0, r1);
        unpack2(acc1, r2, r3);
        if (v0) out[(size_t)n0 * CCH + c] = r0;
        if (v1) out[(size_t)n1 * CCH + c] = r1;
        if (v2) out[(size_t)n2 * CCH + c] = r2;
        if (v3) out[(size_t)n3 * CCH + c] = r3;
    }
}

extern "C" void kernel_launch(void* const* d_in, const int* in_sizes, int n_in,
                              void* d_out, int out_size) {
    const float* feats = (const float*)d_in[0];  // [N, C, I]
    const float* U2    = (const float*)d_in[1];  // [I, I, I, K2]
    const float* U1    = (const float*)d_in[2];  // [I, I, K1]
    const float* U0    = (const float*)d_in[3];  // [I, K0]
    const float* w2    = (const float*)d_in[4];  // [K2, C]
    const float* w1    = (const float*)d_in[5];  // [K1, C]
    const float* w0    = (const float*)d_in[6];  // [K0, C]
    float* out = (float*)d_out;                  // [N, C]

    const int Natoms = in_sizes[0] / (CCH * NI);
    const int nTiles = (Natoms + 1023) / 1024;
    const int nItems = nTiles * CCH;

    const int symElems = RUN_TOTAL * NK2 + NPAIR * NK1;
    sym_kernel<<<(symElems + 255) / 256, 256>>>(U2, U1);
    gemm_kernel<<<57, 256>>>(w2, w1, w0, U0);

    contract_kernel<<<304, 256>>>(feats, out, Natoms, nItems);
}